// round 15
// baseline (speedup 1.0000x reference)
#include <cuda_runtime.h>
#include <cuda_fp16.h>

// out[b,o] = min_i max(x[b,i], w[i,o])   (forward of STE expr == hard min-max)
//
// R14 lesson: pipelining was neutral -> the scan is NOT latency-serialized;
// it's serialized on the per-round __all_sync exit check (next round's loads
// are control-dependent on a ballot fed by this round's loads).
//
// R15: PRECOMPUTED STOP POINT. Scan candidates 0..31 (sorted by x), reduce
// m32 = warp's max-over-128-o best. best only decreases, so any candidate
// with value >= m32 can never improve anything. The sort's end-offset table
// gives the first such position in O(1): kstop = offs[ceil(m32*256)-1].
// Then stream [32, kstop) with ZERO checks -- the loop back-edge depends
// only on the counter, so successive iterations' LDGs overlap freely.
// Exact: positions >= kstop have bin >= ibin => value >= ibin/256 >= m32.
//
// fp16 RN rounding bounds rel err by ~2^-11 < 1e-3.

#define DB 512
#define DI 512
#define DO 1024
#define NBIN 256

__device__ __half g_wh[DI * DO];   // fp16 w, 1 MB

// ---------- Kernel 1: w fp32 -> fp16, chip-wide MLP, ~0.5us ----------
__global__ __launch_bounds__(256) void k_convert(const float* __restrict__ w) {
    int t = blockIdx.x * 256 + threadIdx.x;          // 512 blocks, 1 float4 each
    float4 v = reinterpret_cast<const float4*>(w)[t];
    __half2 h0 = __floats2half2_rn(v.x, v.y);
    __half2 h1 = __floats2half2_rn(v.z, v.w);
    reinterpret_cast<uint2*>(g_wh)[t] =
        make_uint2(*reinterpret_cast<unsigned*>(&h0),
                   *reinterpret_cast<unsigned*>(&h1));
}

// ---------- Kernel 2: fused sort + stop-point scan ----------
__global__ __launch_bounds__(256) void k_fused(const float* __restrict__ x,
                                               float* __restrict__ out) {
    __shared__ uint2 sx[DI];      // bin-ordered {dup-half2(x), idx}, 4 KB
    __shared__ int hist[NBIN];
    __shared__ int offs[NBIN];    // after scatter: END offset of each bin
    __shared__ int wsum[8];

    const int b = blockIdx.x;
    const int tid = threadIdx.x;
    const int lane = tid & 31, wid = tid >> 5;

    // ---- phase 1: counting sort of x[b,:] by half-rounded value ----
    hist[tid] = 0;
    __syncthreads();

    __half h0s = __float2half_rn(x[b * DI + tid]);
    __half h1s = __float2half_rn(x[b * DI + tid + 256]);
    int bin0 = min(NBIN - 1, (int)(__half2float(h0s) * (float)NBIN));
    int bin1 = min(NBIN - 1, (int)(__half2float(h1s) * (float)NBIN));
    atomicAdd(&hist[bin0], 1);
    atomicAdd(&hist[bin1], 1);
    __syncthreads();

    // exclusive prefix over 256 bins (thread t owns bin t)
    int pv = hist[tid];
#pragma unroll
    for (int off = 1; off < 32; off <<= 1) {
        int n = __shfl_up_sync(0xffffffffu, pv, off);
        if (lane >= off) pv += n;
    }
    if (lane == 31) wsum[wid] = pv;
    __syncthreads();
    if (tid < 8) {
        int s = wsum[tid];
#pragma unroll
        for (int off = 1; off < 8; off <<= 1) {
            int n = __shfl_up_sync(0xffu, s, off);
            if (tid >= off) s += n;
        }
        wsum[tid] = s;
    }
    __syncthreads();
    offs[tid] = pv + (wid ? wsum[wid - 1] : 0) - hist[tid];
    __syncthreads();

    {
        unsigned u0 = (unsigned)__half_as_ushort(h0s);
        unsigned u1 = (unsigned)__half_as_ushort(h1s);
        int p0 = atomicAdd(&offs[bin0], 1);
        sx[p0] = make_uint2(u0 | (u0 << 16), (unsigned)tid);
        int p1 = atomicAdd(&offs[bin1], 1);
        sx[p1] = make_uint2(u1 | (u1 << 16), (unsigned)(tid + 256));
    }
    __syncthreads();   // sx ready; offs[] now holds END offsets per bin

    // ---- phase 2: scan first 32 candidates (two 16-batches, no checks) ----
    const unsigned infu = 0x7C007C00u;   // {+inf,+inf} fp16
    __half2 best0 = *reinterpret_cast<const __half2*>(&infu);
    __half2 best1 = best0;

    const __half* wb = g_wh + wid * 128 + lane * 4;   // warp owns 128 o

#pragma unroll
    for (int half = 0; half < 2; half++) {
        __half2 cx[16]; uint2 cw[16];
#pragma unroll
        for (int kk = 0; kk < 16; kk++) {            // 16 LDS+LDG batched
            uint2 e = sx[half * 16 + kk];
            cx[kk] = *reinterpret_cast<__half2*>(&e.x);
            cw[kk] = *reinterpret_cast<const uint2*>(wb + (e.y << 10));
        }
#pragma unroll
        for (int kk = 0; kk < 16; kk++) {
            best0 = __hmin2(best0, __hmax2(cx[kk], *reinterpret_cast<__half2*>(&cw[kk].x)));
            best1 = __hmin2(best1, __hmax2(cx[kk], *reinterpret_cast<__half2*>(&cw[kk].y)));
        }
    }

    // ---- phase 3: compute per-warp stop point from m32 ----
    __half2 m2 = __hmax2(best0, best1);
    float m = fmaxf(__low2float(m2), __high2float(m2));
#pragma unroll
    for (int off = 16; off; off >>= 1)
        m = fmaxf(m, __shfl_xor_sync(0xffffffffu, m, off));

    // first bin whose floor >= m: candidates there can never improve best
    int ibin = min(NBIN, max(1, (int)ceilf(m * (float)NBIN)));
    int kstop = offs[ibin - 1];               // end offset of bin ibin-1
    kstop = min(DI, (kstop + 15) & ~15);      // round up (extra cands harmless)

    // ---- phase 4: stream [32, kstop) with ZERO checks ----
    // Back-edge depends only on k, so iteration n+1's LDGs overlap iter n's.
#pragma unroll 1
    for (int k = 32; k < kstop; k += 16) {
        __half2 cx[16]; uint2 cw[16];
#pragma unroll
        for (int kk = 0; kk < 16; kk++) {
            uint2 e = sx[k + kk];
            cx[kk] = *reinterpret_cast<__half2*>(&e.x);
            cw[kk] = *reinterpret_cast<const uint2*>(wb + (e.y << 10));
        }
#pragma unroll
        for (int kk = 0; kk < 16; kk++) {
            best0 = __hmin2(best0, __hmax2(cx[kk], *reinterpret_cast<__half2*>(&cw[kk].x)));
            best1 = __hmin2(best1, __hmax2(cx[kk], *reinterpret_cast<__half2*>(&cw[kk].y)));
        }
    }

    float4 r;
    r.x = __low2float(best0);  r.y = __high2float(best0);
    r.z = __low2float(best1);  r.w = __high2float(best1);
    *reinterpret_cast<float4*>(&out[b * DO + wid * 128 + lane * 4]) = r;
}

extern "C" void kernel_launch(void* const* d_in, const int* in_sizes, int n_in,
                              void* d_out, int out_size) {
    const float* x = (const float*)d_in[0];   // [512, 512]
    const float* w = (const float*)d_in[1];   // [512, 1024]
    float* out = (float*)d_out;               // [512, 1024]

    k_convert<<<512, 256>>>(w);               // w -> fp16, ~0.5 us
    k_fused<<<DB, 256>>>(x, out);             // one block per row
}

// round 16
// speedup vs baseline: 1.3953x; 1.3953x over previous
#include <cuda_runtime.h>
#include <cuda_fp16.h>

// out[b,o] = min_i max(x[b,i], w[i,o])   (forward of STE expr == hard min-max)
//
// Config = R8 (best measured: 8 warps x 128 o, fp16 LDG.64 gathers, iterative
// warp-uniform exit), with two trims driven by the linear-in-candidates model:
//   (1) no exit check until k=32, then every 8 (halves overshoot; no warp
//       exits before ~35 anyway),
//   (2) scatter stores PRE-SCALED byte offset (idx<<11) so the inner loop is
//       LDS.64 / IADD / LDG.64 / 4x HMNMX2 -- no per-candidate shift.
//
// Scan order: increasing x via 256-bin bucket sort. Warp exits when
// bin_floor(next x) >= max of its lanes' bests: all remaining i have
// x_i >= bound >= best, so max(x_i,w) >= best. Exact, order-independent.
// fp16 RN rounding bounds rel err by ~2^-11 < 1e-3.

#define DB 512
#define DI 512
#define DO 1024
#define NBIN 256

__device__ __half g_wh[DI * DO];   // fp16 w, 1 MB

// ---------- Kernel 1: w fp32 -> fp16, chip-wide MLP, ~0.5us ----------
__global__ __launch_bounds__(256) void k_convert(const float* __restrict__ w) {
    int t = blockIdx.x * 256 + threadIdx.x;          // 512 blocks, 1 float4 each
    float4 v = reinterpret_cast<const float4*>(w)[t];
    __half2 h0 = __floats2half2_rn(v.x, v.y);
    __half2 h1 = __floats2half2_rn(v.z, v.w);
    reinterpret_cast<uint2*>(g_wh)[t] =
        make_uint2(*reinterpret_cast<unsigned*>(&h0),
                   *reinterpret_cast<unsigned*>(&h1));
}

// ---------- Kernel 2: fused sort + pruned scan ----------
__global__ __launch_bounds__(256) void k_fused(const float* __restrict__ x,
                                               float* __restrict__ out) {
    __shared__ uint2 sx[DI];      // bin-ordered {dup-half2(x), byte-offset}, 4 KB
    __shared__ int hist[NBIN];
    __shared__ int offs[NBIN];
    __shared__ int wsum[8];

    const int b = blockIdx.x;
    const int tid = threadIdx.x;
    const int lane = tid & 31, wid = tid >> 5;

    // ---- phase 1: counting sort of x[b,:] by half-rounded value ----
    hist[tid] = 0;
    __syncthreads();

    __half h0s = __float2half_rn(x[b * DI + tid]);
    __half h1s = __float2half_rn(x[b * DI + tid + 256]);
    int bin0 = min(NBIN - 1, (int)(__half2float(h0s) * (float)NBIN));
    int bin1 = min(NBIN - 1, (int)(__half2float(h1s) * (float)NBIN));
    atomicAdd(&hist[bin0], 1);
    atomicAdd(&hist[bin1], 1);
    __syncthreads();

    // exclusive prefix over 256 bins (thread t owns bin t)
    int pv = hist[tid];
#pragma unroll
    for (int off = 1; off < 32; off <<= 1) {
        int n = __shfl_up_sync(0xffffffffu, pv, off);
        if (lane >= off) pv += n;
    }
    if (lane == 31) wsum[wid] = pv;
    __syncthreads();
    if (tid < 8) {
        int s = wsum[tid];
#pragma unroll
        for (int off = 1; off < 8; off <<= 1) {
            int n = __shfl_up_sync(0xffu, s, off);
            if (tid >= off) s += n;
        }
        wsum[tid] = s;
    }
    __syncthreads();
    offs[tid] = pv + (wid ? wsum[wid - 1] : 0) - hist[tid];
    __syncthreads();

    {
        unsigned u0 = (unsigned)__half_as_ushort(h0s);
        unsigned u1 = (unsigned)__half_as_ushort(h1s);
        int p0 = atomicAdd(&offs[bin0], 1);
        sx[p0] = make_uint2(u0 | (u0 << 16), (unsigned)tid << 11);          // byte off = idx*2048
        int p1 = atomicAdd(&offs[bin1], 1);
        sx[p1] = make_uint2(u1 | (u1 << 16), (unsigned)(tid + 256) << 11);
    }
    __syncthreads();

    // ---- phase 2: pruned scan; warp wid owns o = wid*128 .. +127 ----
    const unsigned infu = 0x7C007C00u;   // {+inf,+inf} fp16
    __half2 best0 = *reinterpret_cast<const __half2*>(&infu);
    __half2 best1 = best0;

    const char* wb = reinterpret_cast<const char*>(g_wh + wid * 128 + lane * 4);

    // first 32 candidates unchecked (no warp exits before ~35): 2 batches of 16
#pragma unroll
    for (int half = 0; half < 2; half++) {
#pragma unroll
        for (int kk = 0; kk < 16; kk++) {
            uint2 e = sx[half * 16 + kk];
            __half2 xv = *reinterpret_cast<__half2*>(&e.x);
            uint2 wv = *reinterpret_cast<const uint2*>(wb + e.y);
            best0 = __hmin2(best0, __hmax2(xv, *reinterpret_cast<__half2*>(&wv.x)));
            best1 = __hmin2(best1, __hmax2(xv, *reinterpret_cast<__half2*>(&wv.y)));
        }
    }

    // then check every 8 candidates
#pragma unroll 1
    for (int k = 32; k < DI; k += 8) {
        // lower bound for all candidates at position >= k: same-or-later bin,
        // so value >= bin_floor(value at position k).
        unsigned nx = sx[k].x & 0xFFFFu;
        float nv = __half2float(__ushort_as_half((unsigned short)nx));
        int nbin = min(NBIN - 1, (int)(nv * (float)NBIN));
        float bound = (float)nbin * (1.0f / (float)NBIN);
        __half2 m2 = __hmax2(best0, best1);
        float m = fmaxf(__low2float(m2), __high2float(m2));
        if (__all_sync(0xffffffffu, bound >= m)) break;   // warp-uniform exit

        // unpredicated gather body -> 8 LDG.64 front-batched
#pragma unroll
        for (int kk = 0; kk < 8; kk++) {
            uint2 e = sx[k + kk];
            __half2 xv = *reinterpret_cast<__half2*>(&e.x);
            uint2 wv = *reinterpret_cast<const uint2*>(wb + e.y);
            best0 = __hmin2(best0, __hmax2(xv, *reinterpret_cast<__half2*>(&wv.x)));
            best1 = __hmin2(best1, __hmax2(xv, *reinterpret_cast<__half2*>(&wv.y)));
        }
    }

    float4 r;
    r.x = __low2float(best0);  r.y = __high2float(best0);
    r.z = __low2float(best1);  r.w = __high2float(best1);
    *reinterpret_cast<float4*>(&out[b * DO + wid * 128 + lane * 4]) = r;
}

extern "C" void kernel_launch(void* const* d_in, const int* in_sizes, int n_in,
                              void* d_out, int out_size) {
    const float* x = (const float*)d_in[0];   // [512, 512]
    const float* w = (const float*)d_in[1];   // [512, 1024]
    float* out = (float*)d_out;               // [512, 1024]

    k_convert<<<512, 256>>>(w);               // w -> fp16, ~0.5 us
    k_fused<<<DB, 256>>>(x, out);             // one block per row
}